// round 1
// baseline (speedup 1.0000x reference)
#include <cuda_runtime.h>
#include <math.h>

#define Bdim 32
#define Sdim 2048
#define ENC  1024
#define DEC  1024
#define WTOT 2048
#define NEGV (-1e10f)

#define BM 128
#define BN 128
#define BK 8
#define TM 8
#define TN 8

// Scratch (no cudaMalloc allowed)
__device__ float g_hpb[Bdim * DEC];     // h_proj + bias
__device__ float g_logits[Bdim * Sdim]; // pre-softmax logits

// ---------------------------------------------------------------------------
// Kernel 1: hpb[b][k] = sum_d hidden[b][d] * attn_w[k][d] + attn_b[k]
// grid = DEC blocks (one per k), 256 threads: 8 lanes per batch, 32 batches.
// ---------------------------------------------------------------------------
__global__ void hproj_kernel(const float* __restrict__ hidden,
                             const float* __restrict__ attn_w,
                             const float* __restrict__ attn_b) {
    int k = blockIdx.x;
    __shared__ float ws[DEC];
    for (int d = threadIdx.x; d < DEC; d += blockDim.x)
        ws[d] = attn_w[(size_t)k * WTOT + d];
    __syncthreads();
    int b = threadIdx.x >> 3;
    int l = threadIdx.x & 7;
    const float* h = hidden + b * DEC;
    float p = 0.f;
#pragma unroll 8
    for (int d = l; d < DEC; d += 8) p += h[d] * ws[d];
    p += __shfl_down_sync(0xffffffffu, p, 4, 8);
    p += __shfl_down_sync(0xffffffffu, p, 2, 8);
    p += __shfl_down_sync(0xffffffffu, p, 1, 8);
    if (l == 0) g_hpb[b * DEC + k] = p + attn_b[k];
}

// ---------------------------------------------------------------------------
// Kernel 2 (dominant): fused energy GEMM + tanh + v_w reduction.
// logits[m] = sum_k tanh( sum_e enc[m][e]*w_e[k][e] + hpb[b][k] ) * v_w[k]
// Block = 128 rows of m (all in one batch). Loops 8 k-tiles of 128.
// Classic 128x128x8 smem tile, 8x8 register microtile, 256 threads.
// ---------------------------------------------------------------------------
__global__ __launch_bounds__(256) void energy_kernel(
    const float* __restrict__ enc,
    const float* __restrict__ attn_w,
    const float* __restrict__ v_w) {
    __shared__ float As[BK][BM + 4];   // +4 pad: conflict-free transposed stores
    __shared__ float Bs[BK][BM + 4];
    __shared__ float red[BM][17];

    int tid = threadIdx.x;
    int tc = tid & 15;
    int tr = tid >> 4;
    int m0 = blockIdx.x * BM;
    int bb = m0 >> 11;                 // m0 / Sdim : batch index (constant per block)
    const float* Abase = enc + (size_t)m0 * ENC;
    int lrow = tid >> 1;               // 0..127
    int lcol = (tid & 1) * 4;          // 0 or 4

    float logit_part[TM];
#pragma unroll
    for (int i = 0; i < TM; i++) logit_part[i] = 0.f;

    for (int k0 = 0; k0 < DEC; k0 += BN) {
        float acc[TM][TN];
#pragma unroll
        for (int i = 0; i < TM; i++)
#pragma unroll
            for (int j = 0; j < TN; j++) acc[i][j] = 0.f;

        const float* Bbase = attn_w + (size_t)k0 * WTOT + DEC;  // w_e rows

        for (int e0 = 0; e0 < ENC; e0 += BK) {
            float4 av = *(const float4*)(Abase + (size_t)lrow * ENC  + e0 + lcol);
            float4 bv = *(const float4*)(Bbase + (size_t)lrow * WTOT + e0 + lcol);
            As[lcol + 0][lrow] = av.x;
            As[lcol + 1][lrow] = av.y;
            As[lcol + 2][lrow] = av.z;
            As[lcol + 3][lrow] = av.w;
            Bs[lcol + 0][lrow] = bv.x;
            Bs[lcol + 1][lrow] = bv.y;
            Bs[lcol + 2][lrow] = bv.z;
            Bs[lcol + 3][lrow] = bv.w;
            __syncthreads();
#pragma unroll
            for (int e = 0; e < BK; e++) {
                float a[TM], bf[TN];
                *(float4*)(a)      = *(const float4*)(&As[e][tr * TM]);
                *(float4*)(a + 4)  = *(const float4*)(&As[e][tr * TM + 4]);
                *(float4*)(bf)     = *(const float4*)(&Bs[e][tc * TN]);
                *(float4*)(bf + 4) = *(const float4*)(&Bs[e][tc * TN + 4]);
#pragma unroll
                for (int i = 0; i < TM; i++)
#pragma unroll
                    for (int j = 0; j < TN; j++)
                        acc[i][j] += a[i] * bf[j];
            }
            __syncthreads();
        }

        // Epilogue for this k-tile: tanh + v_w partial reduction (registers only)
#pragma unroll
        for (int j = 0; j < TN; j++) {
            int k = k0 + tc * TN + j;
            float hp = g_hpb[bb * DEC + k];
            float vw = v_w[k];
#pragma unroll
            for (int i = 0; i < TM; i++)
                logit_part[i] += tanhf(acc[i][j] + hp) * vw;
        }
    }

    // Cross-thread (tc) reduction of row partials
#pragma unroll
    for (int i = 0; i < TM; i++) red[tr * TM + i][tc] = logit_part[i];
    __syncthreads();
    if (tid < BM) {
        float s = 0.f;
#pragma unroll
        for (int j = 0; j < 16; j++) s += red[tid][j];
        g_logits[m0 + tid] = s;
    }
}

// ---------------------------------------------------------------------------
// Kernel 3: masked softmax over S per batch. Writes weights to out[B*DEC ...].
// ---------------------------------------------------------------------------
__global__ void softmax_kernel(const int* __restrict__ mask,
                               float* __restrict__ out) {
    int b = blockIdx.x;
    __shared__ float sh[Sdim];
    __shared__ float warpred[8];
    int tid = threadIdx.x;  // 256

    float lmax = -1e30f;
    for (int s = tid; s < Sdim; s += 256) {
        float v = (mask[b * Sdim + s] == 0) ? NEGV : g_logits[b * Sdim + s];
        sh[s] = v;
        lmax = fmaxf(lmax, v);
    }
#pragma unroll
    for (int o = 16; o; o >>= 1) lmax = fmaxf(lmax, __shfl_xor_sync(~0u, lmax, o));
    if ((tid & 31) == 0) warpred[tid >> 5] = lmax;
    __syncthreads();
    if (tid < 32) {
        float v = (tid < 8) ? warpred[tid] : -1e30f;
#pragma unroll
        for (int o = 4; o; o >>= 1) v = fmaxf(v, __shfl_xor_sync(~0u, v, o));
        if (tid == 0) warpred[0] = v;
    }
    __syncthreads();
    float gmax = warpred[0];

    float lsum = 0.f;
    for (int s = tid; s < Sdim; s += 256) {
        float e = expf(sh[s] - gmax);
        sh[s] = e;
        lsum += e;
    }
    __syncthreads();
#pragma unroll
    for (int o = 16; o; o >>= 1) lsum += __shfl_xor_sync(~0u, lsum, o);
    if ((tid & 31) == 0) warpred[tid >> 5] = lsum;
    __syncthreads();
    if (tid < 32) {
        float v = (tid < 8) ? warpred[tid] : 0.f;
#pragma unroll
        for (int o = 4; o; o >>= 1) v += __shfl_xor_sync(~0u, v, o);
        if (tid == 0) warpred[0] = v;
    }
    __syncthreads();
    float inv = 1.f / warpred[0];

    float* w = out + Bdim * DEC;  // weights section of output
    for (int s = tid; s < Sdim; s += 256)
        w[b * Sdim + s] = sh[s] * inv;
}

// ---------------------------------------------------------------------------
// Kernel 4: context[b][e] = sum_s weights[b][s] * enc[b][s][e]
// grid (ENC/256, B), unroll 16 for DRAM MLP. ~256 MB streamed.
// ---------------------------------------------------------------------------
__global__ void context_kernel(const float* __restrict__ enc,
                               const float* __restrict__ w,
                               float* __restrict__ ctx) {
    int b = blockIdx.y;
    int e = blockIdx.x * 256 + threadIdx.x;
    const float* ep = enc + (size_t)b * Sdim * ENC + e;
    const float* wp = w + b * Sdim;
    float acc = 0.f;
    for (int s = 0; s < Sdim; s += 16) {
        float part = 0.f;
#pragma unroll
        for (int u = 0; u < 16; u++)
            part += wp[s + u] * ep[(size_t)(s + u) * ENC];
        acc += part;
    }
    ctx[b * DEC + e] = acc;
}

// ---------------------------------------------------------------------------
extern "C" void kernel_launch(void* const* d_in, const int* in_sizes, int n_in,
                              void* d_out, int out_size) {
    const float* hidden = (const float*)d_in[0];
    const float* enc    = (const float*)d_in[1];
    const int*   mask   = (const int*)d_in[2];
    const float* attn_w = (const float*)d_in[3];
    const float* attn_b = (const float*)d_in[4];
    const float* v_w    = (const float*)d_in[5];
    float* out = (float*)d_out;   // [context(32*1024), weights(32*2048)]

    hproj_kernel<<<DEC, 256>>>(hidden, attn_w, attn_b);
    energy_kernel<<<(Bdim * Sdim) / BM, 256>>>(enc, attn_w, v_w);
    softmax_kernel<<<Bdim, 256>>>(mask, out);
    context_kernel<<<dim3(ENC / 256, Bdim), 256>>>(enc, out + Bdim * DEC, out);
}

// round 3
// speedup vs baseline: 3.4595x; 3.4595x over previous
#include <cuda_runtime.h>
#include <math.h>
#include <stdint.h>

#define Bdim 32
#define Sdim 2048
#define ENC  1024
#define DEC  1024
#define WTOT 2048
#define NEGV (-1e10f)

// ---------------- scratch ---------------------------------------------------
__device__ float g_weT[DEC * ENC];           // tf32-rounded w_e [n][k]
__device__ float g_hpb[Bdim * DEC];          // h_proj + bias
__device__ float g_part[Bdim * Sdim * 4];    // per-(m, ntile) logit partials
__device__ float g_ctx_part[8 * Bdim * ENC]; // split-S context partials

// ---------------- helpers ----------------------------------------------------
__device__ __forceinline__ uint32_t smem_u32(const void* p) {
    uint32_t a;
    asm("{ .reg .u64 t; cvta.to.shared.u64 t, %1; cvt.u32.u64 %0, t; }"
        : "=r"(a) : "l"(p));
    return a;
}
__device__ __forceinline__ uint32_t f2tf32u(float x) {
    uint32_t u;
    asm("cvt.rna.tf32.f32 %0, %1;" : "=r"(u) : "f"(x));
    return u;
}
__device__ __forceinline__ float f2tf32(float x) { return __uint_as_float(f2tf32u(x)); }

__device__ __forceinline__ void mma_tf32(float* d, uint32_t a0, uint32_t a1,
                                         uint32_t a2, uint32_t a3,
                                         uint32_t b0, uint32_t b1) {
    asm volatile(
        "mma.sync.aligned.m16n8k8.row.col.f32.tf32.tf32.f32 "
        "{%0,%1,%2,%3}, {%4,%5,%6,%7}, {%8,%9}, {%0,%1,%2,%3};"
        : "+f"(d[0]), "+f"(d[1]), "+f"(d[2]), "+f"(d[3])
        : "r"(a0), "r"(a1), "r"(a2), "r"(a3), "r"(b0), "r"(b1));
}

// ---------------- preround w_e ----------------------------------------------
__global__ void preround_we(const float* __restrict__ attn_w) {
    int i = blockIdx.x * 256 + threadIdx.x;
    for (int j = i; j < DEC * ENC; j += gridDim.x * 256) {
        int k = j >> 10, e = j & 1023;
        g_weT[j] = f2tf32(attn_w[(size_t)k * WTOT + DEC + e]);
    }
}

// ---------------- h_proj + bias ---------------------------------------------
__global__ void hproj_kernel(const float* __restrict__ hidden,
                             const float* __restrict__ attn_w,
                             const float* __restrict__ attn_b) {
    int k = blockIdx.x;
    __shared__ float ws[DEC];
    for (int d = threadIdx.x; d < DEC; d += blockDim.x)
        ws[d] = attn_w[(size_t)k * WTOT + d];
    __syncthreads();
    int b = threadIdx.x >> 3, l = threadIdx.x & 7;
    const float* h = hidden + b * DEC;
    float p = 0.f;
#pragma unroll 8
    for (int d = l; d < DEC; d += 8) p += h[d] * ws[d];
    p += __shfl_down_sync(0xffffffffu, p, 4, 8);
    p += __shfl_down_sync(0xffffffffu, p, 2, 8);
    p += __shfl_down_sync(0xffffffffu, p, 1, 8);
    if (l == 0) g_hpb[b * DEC + k] = p + attn_b[k];
}

// ---------------- energy GEMM: tf32 mma.sync --------------------------------
// Block tile: 128 rows (M) x 256 cols (N=k_out), K=1024 streamed in BK=16.
// 8 warps as 2x4; warp tile 64x64 via m16n8k8 (4 m-frag x 8 n-frag).
// smem rows padded to 20 floats -> conflict-free fragment gathers.
// Epilogue fuses tanh(d + hpb)*v_w partial reduction -> g_part[m][nt].
#define NCHUNK 64
#define STG_F  7680            // floats per stage: A 128*20 + B 256*20
#define DYN_SMEM (3 * STG_F * 4)

__device__ __forceinline__ void issue_chunk(uint32_t sbase, int stage, int chunk,
                                            int m0, int n0, int tid,
                                            const float* __restrict__ enc) {
    uint32_t sb = sbase + stage * (STG_F * 4);
    int k0 = chunk * 16;
#pragma unroll
    for (int t = 0; t < 6; ++t) {
        int u = t * 256 + tid;                  // 0..1535 16B units
        const float* g;
        uint32_t so;
        if (u < 512) {                          // A: 128 rows x 4 segs
            int r = u >> 2, seg = u & 3;
            so = (uint32_t)(r * 20 + seg * 4) * 4;
            g = enc + (size_t)(m0 + r) * ENC + k0 + seg * 4;
        } else {                                // B: 256 rows x 4 segs
            int v = u - 512;
            int r = v >> 2, seg = v & 3;
            so = (uint32_t)(2560 + r * 20 + seg * 4) * 4;
            g = g_weT + (size_t)(n0 + r) * ENC + k0 + seg * 4;
        }
        asm volatile("cp.async.cg.shared.global [%0], [%1], 16;"
                     :: "r"(sb + so), "l"(g));
    }
    asm volatile("cp.async.commit_group;" ::: "memory");
}

__global__ __launch_bounds__(256, 1) void energy_kernel(
    const float* __restrict__ enc, const float* __restrict__ v_w) {
    extern __shared__ float sm[];
    __shared__ float red[128][4];
    uint32_t sbase = smem_u32(sm);

    int tid = threadIdx.x;
    int wid = tid >> 5, lane = tid & 31;
    int wm = wid >> 2, wn = wid & 3;           // 2x4 warp grid
    int ty = lane >> 2, tx = lane & 3;
    int nt = blockIdx.x, mt = blockIdx.y;
    int m0 = mt * 128, n0 = nt * 256;
    int bb = m0 >> 11;                          // batch index

    float acc[4][8][4];
#pragma unroll
    for (int mi = 0; mi < 4; ++mi)
#pragma unroll
        for (int ni = 0; ni < 8; ++ni)
#pragma unroll
            for (int c = 0; c < 4; ++c) acc[mi][ni][c] = 0.f;

    issue_chunk(sbase, 0, 0, m0, n0, tid, enc);
    issue_chunk(sbase, 1, 1, m0, n0, tid, enc);

    for (int i = 0; i < NCHUNK; ++i) {
        if (i + 2 < NCHUNK) asm volatile("cp.async.wait_group 1;" ::: "memory");
        else                asm volatile("cp.async.wait_group 0;" ::: "memory");
        __syncthreads();
        if (i + 2 < NCHUNK)
            issue_chunk(sbase, (i + 2) % 3, i + 2, m0, n0, tid, enc);

        const float* Asf = sm + (i % 3) * STG_F;
        const float* Bsf = Asf + 2560;
#pragma unroll
        for (int ks = 0; ks < 2; ++ks) {
            int kb = ks * 8;
            uint32_t bf[8][2];
#pragma unroll
            for (int ni = 0; ni < 8; ++ni) {
                const float* bp = Bsf + (wn * 64 + ni * 8 + ty) * 20 + kb + tx;
                bf[ni][0] = __float_as_uint(bp[0]);   // pre-rounded tf32 bits
                bf[ni][1] = __float_as_uint(bp[4]);
            }
#pragma unroll
            for (int mi = 0; mi < 4; ++mi) {
                const float* ap = Asf + (wm * 64 + mi * 16 + ty) * 20 + kb + tx;
                uint32_t a0 = f2tf32u(ap[0]);
                uint32_t a1 = f2tf32u(ap[160]);
                uint32_t a2 = f2tf32u(ap[4]);
                uint32_t a3 = f2tf32u(ap[164]);
#pragma unroll
                for (int ni = 0; ni < 8; ++ni)
                    mma_tf32(acc[mi][ni], a0, a1, a2, a3, bf[ni][0], bf[ni][1]);
            }
        }
    }

    // Epilogue: tanh + v_w reduction over this block's 256 cols.
    int colbase = n0 + wn * 64 + tx * 2;
    int hb = bb * DEC;
    float pr[4][2];
#pragma unroll
    for (int mi = 0; mi < 4; ++mi) { pr[mi][0] = 0.f; pr[mi][1] = 0.f; }
#pragma unroll
    for (int ni = 0; ni < 8; ++ni) {
        int c0 = colbase + ni * 8;
        float hp0 = g_hpb[hb + c0],  hp1 = g_hpb[hb + c0 + 1];
        float vw0 = v_w[c0],         vw1 = v_w[c0 + 1];
#pragma unroll
        for (int mi = 0; mi < 4; ++mi) {
            pr[mi][0] += tanhf(acc[mi][ni][0] + hp0) * vw0
                       + tanhf(acc[mi][ni][1] + hp1) * vw1;
            pr[mi][1] += tanhf(acc[mi][ni][2] + hp0) * vw0
                       + tanhf(acc[mi][ni][3] + hp1) * vw1;
        }
    }
#pragma unroll
    for (int mi = 0; mi < 4; ++mi)
#pragma unroll
        for (int h = 0; h < 2; ++h) {
            float p = pr[mi][h];
            p += __shfl_xor_sync(0xffffffffu, p, 1);
            p += __shfl_xor_sync(0xffffffffu, p, 2);
            if (tx == 0) red[wm * 64 + mi * 16 + h * 8 + ty][wn] = p;
        }
    __syncthreads();
    if (tid < 128)
        g_part[((size_t)(m0 + tid)) * 4 + nt] =
            red[tid][0] + red[tid][1] + red[tid][2] + red[tid][3];
}

// ---------------- masked softmax (sums 4 partials) --------------------------
__global__ void softmax_kernel(const int* __restrict__ mask, float* __restrict__ out) {
    int b = blockIdx.x;
    __shared__ float sh[Sdim];
    __shared__ float wr[8];
    int tid = threadIdx.x;

    float lmax = -1e30f;
    for (int s = tid; s < Sdim; s += 256) {
        float v;
        if (mask[b * Sdim + s] == 0) v = NEGV;
        else {
            float4 pp = ((const float4*)g_part)[b * Sdim + s];
            v = (pp.x + pp.y) + (pp.z + pp.w);
        }
        sh[s] = v;
        lmax = fmaxf(lmax, v);
    }
#pragma unroll
    for (int o = 16; o; o >>= 1) lmax = fmaxf(lmax, __shfl_xor_sync(~0u, lmax, o));
    if ((tid & 31) == 0) wr[tid >> 5] = lmax;
    __syncthreads();
    if (tid < 32) {
        float v = (tid < 8) ? wr[tid] : -1e30f;
#pragma unroll
        for (int o = 4; o; o >>= 1) v = fmaxf(v, __shfl_xor_sync(~0u, v, o));
        if (tid == 0) wr[0] = v;
    }
    __syncthreads();
    float gmax = wr[0];

    float lsum = 0.f;
    for (int s = tid; s < Sdim; s += 256) {
        float e = expf(sh[s] - gmax);
        sh[s] = e;
        lsum += e;
    }
    __syncthreads();
#pragma unroll
    for (int o = 16; o; o >>= 1) lsum += __shfl_xor_sync(~0u, lsum, o);
    if ((tid & 31) == 0) wr[tid >> 5] = lsum;
    __syncthreads();
    if (tid < 32) {
        float v = (tid < 8) ? wr[tid] : 0.f;
#pragma unroll
        for (int o = 4; o; o >>= 1) v += __shfl_xor_sync(~0u, v, o);
        if (tid == 0) wr[0] = v;
    }
    __syncthreads();
    float inv = 1.f / wr[0];
    float* w = out + Bdim * DEC;
    for (int s = tid; s < Sdim; s += 256) w[b * Sdim + s] = sh[s] * inv;
}

// ---------------- context (split-S) -----------------------------------------
__global__ void ctx_part_kernel(const float* __restrict__ enc,
                                const float* __restrict__ w) {
    int e = blockIdx.x * 256 + threadIdx.x;
    int b = blockIdx.y, z = blockIdx.z;
    const float* ep = enc + ((size_t)b * Sdim + z * 256) * ENC + e;
    const float* wp = w + b * Sdim + z * 256;
    float acc = 0.f;
    for (int s = 0; s < 256; s += 8) {
        float part = 0.f;
#pragma unroll
        for (int u = 0; u < 8; ++u)
            part += wp[s + u] * ep[(size_t)(s + u) * ENC];
        acc += part;
    }
    g_ctx_part[((z * Bdim + b) << 10) + e] = acc;
}
__global__ void ctx_reduce_kernel(float* __restrict__ out) {
    int id = blockIdx.x * 256 + threadIdx.x;
    float s = 0.f;
#pragma unroll
    for (int z = 0; z < 8; ++z) s += g_ctx_part[(z << 15) + id];
    out[id] = s;
}

// ---------------------------------------------------------------------------
extern "C" void kernel_launch(void* const* d_in, const int* in_sizes, int n_in,
                              void* d_out, int out_size) {
    const float* hidden = (const float*)d_in[0];
    const float* enc    = (const float*)d_in[1];
    const int*   mask   = (const int*)d_in[2];
    const float* attn_w = (const float*)d_in[3];
    const float* attn_b = (const float*)d_in[4];
    const float* v_w    = (const float*)d_in[5];
    float* out = (float*)d_out;   // [context(32x1024), weights(32x2048)]

    cudaFuncSetAttribute(energy_kernel,
                         cudaFuncAttributeMaxDynamicSharedMemorySize, DYN_SMEM);

    preround_we<<<256, 256>>>(attn_w);
    hproj_kernel<<<DEC, 256>>>(hidden, attn_w, attn_b);
    energy_kernel<<<dim3(4, 512), 256, DYN_SMEM>>>(enc, v_w);
    softmax_kernel<<<Bdim, 256>>>(mask, out);
    ctx_part_kernel<<<dim3(ENC / 256, Bdim, 8), 256>>>(enc, out + Bdim * DEC);
    ctx_reduce_kernel<<<128, 256>>>(out);
}

// round 4
// speedup vs baseline: 5.7219x; 1.6540x over previous
#include <cuda_runtime.h>
#include <cuda_fp16.h>
#include <math.h>
#include <stdint.h>

#define Bdim 32
#define Sdim 2048
#define ENC  1024
#define DEC  1024
#define WTOT 2048
#define NEGV (-1e10f)

// ---------------- scratch ---------------------------------------------------
__device__ uint4 g_encH4[(size_t)Bdim * Sdim * ENC / 8]; // enc as fp16 [m][k]
__device__ uint4 g_weH4[DEC * ENC / 8];                  // w_e as fp16 [n][k]
__device__ float g_hpb[Bdim * DEC];                      // h_proj + bias
__device__ float g_part[Bdim * Sdim * 4];                // per-(m, ntile) partials
__device__ float g_ctx_part[8 * Bdim * ENC];             // split-S ctx partials

// ---------------- helpers ----------------------------------------------------
__device__ __forceinline__ uint32_t smem_u32(const void* p) {
    uint32_t a;
    asm("{ .reg .u64 t; cvta.to.shared.u64 t, %1; cvt.u32.u64 %0, t; }"
        : "=r"(a) : "l"(p));
    return a;
}
__device__ __forceinline__ uint32_t h2pack(float x, float y) {
    __half2 h = __floats2half2_rn(x, y);
    return *(uint32_t*)&h;
}
__device__ __forceinline__ void mma_f16(float* d, uint32_t a0, uint32_t a1,
                                        uint32_t a2, uint32_t a3,
                                        uint32_t b0, uint32_t b1) {
    asm volatile(
        "mma.sync.aligned.m16n8k16.row.col.f32.f16.f16.f32 "
        "{%0,%1,%2,%3}, {%4,%5,%6,%7}, {%8,%9}, {%0,%1,%2,%3};"
        : "+f"(d[0]), "+f"(d[1]), "+f"(d[2]), "+f"(d[3])
        : "r"(a0), "r"(a1), "r"(a2), "r"(a3), "r"(b0), "r"(b1));
}

// ---------------- fp32 -> fp16 conversions ----------------------------------
__global__ void enc_to_half(const float* __restrict__ enc) {
    size_t n8 = (size_t)Bdim * Sdim * ENC / 8;
    size_t stride = (size_t)gridDim.x * blockDim.x;
    for (size_t i = (size_t)blockIdx.x * blockDim.x + threadIdx.x; i < n8; i += stride) {
        float4 f0 = ((const float4*)enc)[2 * i];
        float4 f1 = ((const float4*)enc)[2 * i + 1];
        uint4 o;
        o.x = h2pack(f0.x, f0.y); o.y = h2pack(f0.z, f0.w);
        o.z = h2pack(f1.x, f1.y); o.w = h2pack(f1.z, f1.w);
        g_encH4[i] = o;
    }
}
__global__ void we_to_half(const float* __restrict__ attn_w) {
    int i = blockIdx.x * 256 + threadIdx.x;          // over DEC*ENC/8
    for (int j = i; j < DEC * ENC / 8; j += gridDim.x * 256) {
        int k = j >> 7, seg = j & 127;               // row k, 8-elem segment
        const float* src = attn_w + (size_t)k * WTOT + DEC + seg * 8;
        float4 f0 = ((const float4*)src)[0];
        float4 f1 = ((const float4*)src)[1];
        uint4 o;
        o.x = h2pack(f0.x, f0.y); o.y = h2pack(f0.z, f0.w);
        o.z = h2pack(f1.x, f1.y); o.w = h2pack(f1.z, f1.w);
        g_weH4[j] = o;
    }
}

// ---------------- h_proj + bias ---------------------------------------------
__global__ void hproj_kernel(const float* __restrict__ hidden,
                             const float* __restrict__ attn_w,
                             const float* __restrict__ attn_b) {
    int k = blockIdx.x;
    __shared__ float ws[DEC];
    for (int d = threadIdx.x; d < DEC; d += blockDim.x)
        ws[d] = attn_w[(size_t)k * WTOT + d];
    __syncthreads();
    int b = threadIdx.x >> 3, l = threadIdx.x & 7;
    const float* h = hidden + b * DEC;
    float p = 0.f;
#pragma unroll 8
    for (int d = l; d < DEC; d += 8) p += h[d] * ws[d];
    p += __shfl_down_sync(0xffffffffu, p, 4, 8);
    p += __shfl_down_sync(0xffffffffu, p, 2, 8);
    p += __shfl_down_sync(0xffffffffu, p, 1, 8);
    if (l == 0) g_hpb[b * DEC + k] = p + attn_b[k];
}

// ---------------- energy GEMM: fp16 mma.sync m16n8k16 -----------------------
// Block tile 128(M) x 256(N), K=1024 in 32 chunks of 32. 8 warps 2x4,
// warp tile 64x64 (4 m-frag x 8 n-frag, k16). 4-stage cp.async pipeline.
// smem rows: 32 halves data + 8 pad = 40 halves (20 b32) -> conflict-free.
#define NCHUNK 32
#define A_STG_B 10240            // 128 rows * 80B
#define B_STG_B 20480            // 256 rows * 80B
#define STG_B   (A_STG_B + B_STG_B)
#define DYN_SMEM (4 * STG_B)

__device__ __forceinline__ void issue_chunk(uint32_t sbase, int stage, int chunk,
                                            int m0, int n0, int tid) {
    uint32_t sb = sbase + stage * STG_B;
    int k0 = chunk * 32;                        // in halves
    const __half* encH = (const __half*)g_encH4;
    const __half* weH  = (const __half*)g_weH4;
#pragma unroll
    for (int t = 0; t < 6; ++t) {
        int u = t * 256 + tid;                  // 16B units: A 512, B 1024
        const __half* g;
        uint32_t so;
        if (u < 512) {
            int r = u >> 2, seg = u & 3;
            so = (uint32_t)(r * 80 + seg * 16);
            g = encH + (size_t)(m0 + r) * ENC + k0 + seg * 8;
        } else {
            int v = u - 512;
            int r = v >> 2, seg = v & 3;
            so = (uint32_t)(A_STG_B + r * 80 + seg * 16);
            g = weH + (size_t)(n0 + r) * ENC + k0 + seg * 8;
        }
        asm volatile("cp.async.cg.shared.global [%0], [%1], 16;"
                     :: "r"(sb + so), "l"(g));
    }
    asm volatile("cp.async.commit_group;" ::: "memory");
}

__global__ __launch_bounds__(256, 1) void energy_kernel(const float* __restrict__ v_w) {
    extern __shared__ uint32_t sm[];
    __shared__ float red[128][4];
    uint32_t sbase = smem_u32(sm);

    int tid = threadIdx.x;
    int wid = tid >> 5, lane = tid & 31;
    int wm = wid >> 2, wn = wid & 3;            // 2x4 warp grid
    int ty = lane >> 2, tx = lane & 3;
    int nt = blockIdx.x, mt = blockIdx.y;
    int m0 = mt * 128, n0 = nt * 256;
    int bb = m0 >> 11;

    float acc[4][8][4];
#pragma unroll
    for (int mi = 0; mi < 4; ++mi)
#pragma unroll
        for (int ni = 0; ni < 8; ++ni)
#pragma unroll
            for (int c = 0; c < 4; ++c) acc[mi][ni][c] = 0.f;

    issue_chunk(sbase, 0, 0, m0, n0, tid);
    issue_chunk(sbase, 1, 1, m0, n0, tid);
    issue_chunk(sbase, 2, 2, m0, n0, tid);

    for (int i = 0; i < NCHUNK; ++i) {
        if (i <= NCHUNK - 3)      asm volatile("cp.async.wait_group 2;" ::: "memory");
        else if (i == NCHUNK - 2) asm volatile("cp.async.wait_group 1;" ::: "memory");
        else                      asm volatile("cp.async.wait_group 0;" ::: "memory");
        __syncthreads();
        if (i + 3 < NCHUNK)
            issue_chunk(sbase, (i + 3) & 3, i + 3, m0, n0, tid);

        const uint32_t* Ab = sm + (i & 3) * (STG_B / 4);
        const uint32_t* Bb = Ab + (A_STG_B / 4);
#pragma unroll
        for (int ks = 0; ks < 2; ++ks) {
            int kb = ks * 8;                    // b32 offset within row
            uint32_t bf[8][2];
#pragma unroll
            for (int ni = 0; ni < 8; ++ni) {
                const uint32_t* bp = Bb + (wn * 64 + ni * 8 + ty) * 20 + kb + tx;
                bf[ni][0] = bp[0];
                bf[ni][1] = bp[4];
            }
#pragma unroll
            for (int mi = 0; mi < 4; ++mi) {
                const uint32_t* ap = Ab + (wm * 64 + mi * 16 + ty) * 20 + kb + tx;
                uint32_t a0 = ap[0];
                uint32_t a1 = ap[160];
                uint32_t a2 = ap[4];
                uint32_t a3 = ap[164];
#pragma unroll
                for (int ni = 0; ni < 8; ++ni)
                    mma_f16(acc[mi][ni], a0, a1, a2, a3, bf[ni][0], bf[ni][1]);
            }
        }
    }

    // Epilogue: tanh + v_w partial reduction over this block's 256 cols.
    int colbase = n0 + wn * 64 + tx * 2;
    int hb = bb * DEC;
    float pr[4][2];
#pragma unroll
    for (int mi = 0; mi < 4; ++mi) { pr[mi][0] = 0.f; pr[mi][1] = 0.f; }
#pragma unroll
    for (int ni = 0; ni < 8; ++ni) {
        int c0 = colbase + ni * 8;
        float hp0 = g_hpb[hb + c0],  hp1 = g_hpb[hb + c0 + 1];
        float vw0 = v_w[c0],         vw1 = v_w[c0 + 1];
#pragma unroll
        for (int mi = 0; mi < 4; ++mi) {
            pr[mi][0] += tanhf(acc[mi][ni][0] + hp0) * vw0
                       + tanhf(acc[mi][ni][1] + hp1) * vw1;
            pr[mi][1] += tanhf(acc[mi][ni][2] + hp0) * vw0
                       + tanhf(acc[mi][ni][3] + hp1) * vw1;
        }
    }
#pragma unroll
    for (int mi = 0; mi < 4; ++mi)
#pragma unroll
        for (int h = 0; h < 2; ++h) {
            float p = pr[mi][h];
            p += __shfl_xor_sync(0xffffffffu, p, 1);
            p += __shfl_xor_sync(0xffffffffu, p, 2);
            if (tx == 0) red[wm * 64 + mi * 16 + h * 8 + ty][wn] = p;
        }
    __syncthreads();
    if (tid < 128)
        g_part[((size_t)(m0 + tid)) * 4 + nt] =
            red[tid][0] + red[tid][1] + red[tid][2] + red[tid][3];
}

// ---------------- masked softmax (sums 4 partials) --------------------------
__global__ void softmax_kernel(const int* __restrict__ mask, float* __restrict__ out) {
    int b = blockIdx.x;
    __shared__ float sh[Sdim];
    __shared__ float wr[8];
    int tid = threadIdx.x;

    float lmax = -1e30f;
    for (int s = tid; s < Sdim; s += 256) {
        float v;
        if (mask[b * Sdim + s] == 0) v = NEGV;
        else {
            float4 pp = ((const float4*)g_part)[b * Sdim + s];
            v = (pp.x + pp.y) + (pp.z + pp.w);
        }
        sh[s] = v;
        lmax = fmaxf(lmax, v);
    }
#pragma unroll
    for (int o = 16; o; o >>= 1) lmax = fmaxf(lmax, __shfl_xor_sync(~0u, lmax, o));
    if ((tid & 31) == 0) wr[tid >> 5] = lmax;
    __syncthreads();
    if (tid < 32) {
        float v = (tid < 8) ? wr[tid] : -1e30f;
#pragma unroll
        for (int o = 4; o; o >>= 1) v = fmaxf(v, __shfl_xor_sync(~0u, v, o));
        if (tid == 0) wr[0] = v;
    }
    __syncthreads();
    float gmax = wr[0];

    float lsum = 0.f;
    for (int s = tid; s < Sdim; s += 256) {
        float e = expf(sh[s] - gmax);
        sh[s] = e;
        lsum += e;
    }
    __syncthreads();
#pragma unroll
    for (int o = 16; o; o >>= 1) lsum += __shfl_xor_sync(~0u, lsum, o);
    if ((tid & 31) == 0) wr[tid >> 5] = lsum;
    __syncthreads();
    if (tid < 32) {
        float v = (tid < 8) ? wr[tid] : 0.f;
#pragma unroll
        for (int o = 4; o; o >>= 1) v += __shfl_xor_sync(~0u, v, o);
        if (tid == 0) wr[0] = v;
    }
    __syncthreads();
    float inv = 1.f / wr[0];
    float* w = out + Bdim * DEC;
    for (int s = tid; s < Sdim; s += 256) w[b * Sdim + s] = sh[s] * inv;
}

// ---------------- context (split-S, fp32 enc for accuracy) ------------------
__global__ void ctx_part_kernel(const float* __restrict__ enc,
                                const float* __restrict__ w) {
    int e = blockIdx.x * 256 + threadIdx.x;
    int b = blockIdx.y, z = blockIdx.z;
    const float* ep = enc + ((size_t)b * Sdim + z * 256) * ENC + e;
    const float* wp = w + b * Sdim + z * 256;
    float acc = 0.f;
    for (int s = 0; s < 256; s += 8) {
        float part = 0.f;
#pragma unroll
        for (int u = 0; u < 8; ++u)
            part += wp[s + u] * ep[(size_t)(s + u) * ENC];
        acc += part;
    }
    g_ctx_part[((z * Bdim + b) << 10) + e] = acc;
}
__global__ void ctx_reduce_kernel(float* __restrict__ out) {
    int id = blockIdx.x * 256 + threadIdx.x;
    float s = 0.f;
#pragma unroll
    for (int z = 0; z < 8; ++z) s += g_ctx_part[(z << 15) + id];
    out[id] = s;
}

// ---------------------------------------------------------------------------
extern "C" void kernel_launch(void* const* d_in, const int* in_sizes, int n_in,
                              void* d_out, int out_size) {
    const float* hidden = (const float*)d_in[0];
    const float* enc    = (const float*)d_in[1];
    const int*   mask   = (const int*)d_in[2];
    const float* attn_w = (const float*)d_in[3];
    const float* attn_b = (const float*)d_in[4];
    const float* v_w    = (const float*)d_in[5];
    float* out = (float*)d_out;   // [context(32x1024), weights(32x2048)]

    cudaFuncSetAttribute(energy_kernel,
                         cudaFuncAttributeMaxDynamicSharedMemorySize, DYN_SMEM);

    enc_to_half<<<4096, 256>>>(enc);
    we_to_half<<<128, 256>>>(attn_w);
    hproj_kernel<<<DEC, 256>>>(hidden, attn_w, attn_b);
    energy_kernel<<<dim3(4, 512), 256, DYN_SMEM>>>(v_w);
    softmax_kernel<<<Bdim, 256>>>(mask, out);
    ctx_part_kernel<<<dim3(ENC / 256, Bdim, 8), 256>>>(enc, out + Bdim * DEC);
    ctx_reduce_kernel<<<128, 256>>>(out);
}

// round 5
// speedup vs baseline: 6.4031x; 1.1191x over previous
#include <cuda_runtime.h>
#include <cuda_fp16.h>
#include <math.h>
#include <stdint.h>

#define Bdim 32
#define Sdim 2048
#define ENC  1024
#define DEC  1024
#define WTOT 2048
#define NEGV (-1e10f)

// ---------------- scratch ---------------------------------------------------
__device__ uint4 g_encH4[(size_t)Bdim * Sdim * ENC / 8]; // enc as fp16 [m][k]
__device__ uint4 g_weH4[DEC * ENC / 8];                  // w_e as fp16 [n][k]
__device__ float g_hpb[Bdim * DEC];                      // h_proj + bias
__device__ float g_part[Bdim * Sdim * 4];                // per-(m, ntile) partials
__device__ float g_ctx_part[8 * Bdim * ENC];             // split-S ctx partials

// ---------------- helpers ----------------------------------------------------
__device__ __forceinline__ uint32_t smem_u32(const void* p) {
    uint32_t a;
    asm("{ .reg .u64 t; cvta.to.shared.u64 t, %1; cvt.u32.u64 %0, t; }"
        : "=r"(a) : "l"(p));
    return a;
}
__device__ __forceinline__ uint32_t h2pack(float x, float y) {
    __half2 h = __floats2half2_rn(x, y);
    return *(uint32_t*)&h;
}
__device__ __forceinline__ void mma_f16(float* d, uint32_t a0, uint32_t a1,
                                        uint32_t a2, uint32_t a3,
                                        uint32_t b0, uint32_t b1) {
    asm volatile(
        "mma.sync.aligned.m16n8k16.row.col.f32.f16.f16.f32 "
        "{%0,%1,%2,%3}, {%4,%5,%6,%7}, {%8,%9}, {%0,%1,%2,%3};"
        : "+f"(d[0]), "+f"(d[1]), "+f"(d[2]), "+f"(d[3])
        : "r"(a0), "r"(a1), "r"(a2), "r"(a3), "r"(b0), "r"(b1));
}
#define LDSM4(r0, r1, r2, r3, a) \
    asm volatile("ldmatrix.sync.aligned.m8n8.x4.shared.b16 {%0,%1,%2,%3}, [%4];" \
                 : "=r"(r0), "=r"(r1), "=r"(r2), "=r"(r3) : "r"(a))

// ---------------- fp32 -> fp16 conversions ----------------------------------
__global__ void enc_to_half(const float* __restrict__ enc) {
    size_t n8 = (size_t)Bdim * Sdim * ENC / 8;
    size_t stride = (size_t)gridDim.x * blockDim.x;
    for (size_t i = (size_t)blockIdx.x * blockDim.x + threadIdx.x; i < n8; i += stride) {
        float4 f0 = ((const float4*)enc)[2 * i];
        float4 f1 = ((const float4*)enc)[2 * i + 1];
        uint4 o;
        o.x = h2pack(f0.x, f0.y); o.y = h2pack(f0.z, f0.w);
        o.z = h2pack(f1.x, f1.y); o.w = h2pack(f1.z, f1.w);
        g_encH4[i] = o;
    }
}
__global__ void we_to_half(const float* __restrict__ attn_w) {
    int i = blockIdx.x * 256 + threadIdx.x;
    for (int j = i; j < DEC * ENC / 8; j += gridDim.x * 256) {
        int k = j >> 7, seg = j & 127;
        const float* src = attn_w + (size_t)k * WTOT + DEC + seg * 8;
        float4 f0 = ((const float4*)src)[0];
        float4 f1 = ((const float4*)src)[1];
        uint4 o;
        o.x = h2pack(f0.x, f0.y); o.y = h2pack(f0.z, f0.w);
        o.z = h2pack(f1.x, f1.y); o.w = h2pack(f1.z, f1.w);
        g_weH4[j] = o;
    }
}

// ---------------- h_proj + bias ---------------------------------------------
__global__ void hproj_kernel(const float* __restrict__ hidden,
                             const float* __restrict__ attn_w,
                             const float* __restrict__ attn_b) {
    int k = blockIdx.x;
    __shared__ float ws[DEC];
    for (int d = threadIdx.x; d < DEC; d += blockDim.x)
        ws[d] = attn_w[(size_t)k * WTOT + d];
    __syncthreads();
    int b = threadIdx.x >> 3, l = threadIdx.x & 7;
    const float* h = hidden + b * DEC;
    float p = 0.f;
#pragma unroll 8
    for (int d = l; d < DEC; d += 8) p += h[d] * ws[d];
    p += __shfl_down_sync(0xffffffffu, p, 4, 8);
    p += __shfl_down_sync(0xffffffffu, p, 2, 8);
    p += __shfl_down_sync(0xffffffffu, p, 1, 8);
    if (l == 0) g_hpb[b * DEC + k] = p + attn_b[k];
}

// ---------------- energy GEMM: fp16 mma.sync + ldmatrix ---------------------
// Block tile 128(M) x 256(N), K=1024 in 32 chunks of 32 halves.
// 8 warps 2x4; warp tile 64x64. 6-stage cp.async pipeline, barrier per 2 chunks.
// smem rows: 32 data halves + 8 pad = 80B; ldmatrix groups hit all 32 banks.
#define NCHUNK 32
#define A_STG_B 10240            // 128 rows * 80B
#define B_STG_B 20480            // 256 rows * 80B
#define STG_B   (A_STG_B + B_STG_B)
#define NSTAGE  6
#define DYN_SMEM (NSTAGE * STG_B)

__device__ __forceinline__ void issue_chunk(uint32_t sbase, int stage, int chunk,
                                            int m0, int n0, int tid) {
    uint32_t sb = sbase + stage * STG_B;
    int k0 = chunk * 32;
    const __half* encH = (const __half*)g_encH4;
    const __half* weH  = (const __half*)g_weH4;
#pragma unroll
    for (int t = 0; t < 6; ++t) {
        int u = t * 256 + tid;                  // 16B units: A 512, B 1024
        const __half* g;
        uint32_t so;
        if (u < 512) {
            int r = u >> 2, seg = u & 3;
            so = (uint32_t)(r * 80 + seg * 16);
            g = encH + (size_t)(m0 + r) * ENC + k0 + seg * 8;
        } else {
            int v = u - 512;
            int r = v >> 2, seg = v & 3;
            so = (uint32_t)(A_STG_B + r * 80 + seg * 16);
            g = weH + (size_t)(n0 + r) * ENC + k0 + seg * 8;
        }
        asm volatile("cp.async.cg.shared.global [%0], [%1], 16;"
                     :: "r"(sb + so), "l"(g));
    }
    asm volatile("cp.async.commit_group;" ::: "memory");
}

struct Frag { uint32_t r[4]; };

__global__ __launch_bounds__(256, 1) void energy_kernel(const float* __restrict__ v_w) {
    extern __shared__ uint32_t sm[];
    __shared__ float red[128][4];
    uint32_t sbase = smem_u32(sm);

    int tid = threadIdx.x;
    int wid = tid >> 5, lane = tid & 31;
    int wm = wid >> 2, wn = wid & 3;            // 2x4 warp grid
    int ty = lane >> 2, tx = lane & 3;
    int nt = blockIdx.x, mt = blockIdx.y;
    int m0 = mt * 128, n0 = nt * 256;
    int bb = m0 >> 11;

    // ldmatrix per-lane base byte offsets (within a stage)
    int aRow = wm * 64 + (lane & 7) + (((lane >> 3) & 1) << 3);
    uint32_t aBase = (uint32_t)(aRow * 80 + ((lane >> 4) << 4));
    int bRow = wn * 64 + (lane & 7) + ((lane >> 4) << 3);
    uint32_t bBase = (uint32_t)(A_STG_B + bRow * 80 + (((lane >> 3) & 1) << 4));

    float acc[4][8][4];
#pragma unroll
    for (int mi = 0; mi < 4; ++mi)
#pragma unroll
        for (int ni = 0; ni < 8; ++ni)
#pragma unroll
            for (int c = 0; c < 4; ++c) acc[mi][ni][c] = 0.f;

    issue_chunk(sbase, 0, 0, m0, n0, tid);
    issue_chunk(sbase, 1, 1, m0, n0, tid);
    issue_chunk(sbase, 2, 2, m0, n0, tid);
    issue_chunk(sbase, 3, 3, m0, n0, tid);

    for (int ip = 0; ip < NCHUNK / 2; ++ip) {
        if (ip < NCHUNK / 2 - 1)
            asm volatile("cp.async.wait_group 2;" ::: "memory");
        else
            asm volatile("cp.async.wait_group 0;" ::: "memory");
        __syncthreads();
        {
            int c1 = 2 * ip + 4, c2 = 2 * ip + 5;
            if (c1 < NCHUNK) issue_chunk(sbase, c1 % NSTAGE, c1, m0, n0, tid);
            if (c2 < NCHUNK) issue_chunk(sbase, c2 % NSTAGE, c2, m0, n0, tid);
        }
#pragma unroll
        for (int half = 0; half < 2; ++half) {
            int chunk = 2 * ip + half;
            uint32_t sb = sbase + (chunk % NSTAGE) * STG_B;
#pragma unroll
            for (int ks = 0; ks < 2; ++ks) {
                uint32_t koff = (uint32_t)(ks * 32);
                Frag bf[4];                      // p -> {2p.lo, 2p.hi, 2p+1.lo, 2p+1.hi}
#pragma unroll
                for (int p = 0; p < 4; ++p)
                    LDSM4(bf[p].r[0], bf[p].r[1], bf[p].r[2], bf[p].r[3],
                          sb + bBase + p * 1280 + koff);
                Frag af[2];
                LDSM4(af[0].r[0], af[0].r[1], af[0].r[2], af[0].r[3],
                      sb + aBase + 0 * 1280 + koff);
                LDSM4(af[1].r[0], af[1].r[1], af[1].r[2], af[1].r[3],
                      sb + aBase + 1 * 1280 + koff);
#pragma unroll
                for (int mi = 0; mi < 4; ++mi) {
                    Frag a = af[mi & 1];
                    if (mi + 2 < 4)
                        LDSM4(af[mi & 1].r[0], af[mi & 1].r[1],
                              af[mi & 1].r[2], af[mi & 1].r[3],
                              sb + aBase + (mi + 2) * 1280 + koff);
#pragma unroll
                    for (int p = 0; p < 4; ++p) {
                        mma_f16(acc[mi][2 * p],     a.r[0], a.r[1], a.r[2], a.r[3],
                                bf[p].r[0], bf[p].r[1]);
                        mma_f16(acc[mi][2 * p + 1], a.r[0], a.r[1], a.r[2], a.r[3],
                                bf[p].r[2], bf[p].r[3]);
                    }
                }
            }
        }
    }

    // Epilogue: tanh + v_w partial reduction over this block's 256 cols.
    int colbase = n0 + wn * 64 + tx * 2;
    int hb = bb * DEC;
    float pr[4][2];
#pragma unroll
    for (int mi = 0; mi < 4; ++mi) { pr[mi][0] = 0.f; pr[mi][1] = 0.f; }
#pragma unroll
    for (int ni = 0; ni < 8; ++ni) {
        int c0 = colbase + ni * 8;
        float hp0 = g_hpb[hb + c0],  hp1 = g_hpb[hb + c0 + 1];
        float vw0 = v_w[c0],         vw1 = v_w[c0 + 1];
#pragma unroll
        for (int mi = 0; mi < 4; ++mi) {
            pr[mi][0] += tanhf(acc[mi][ni][0] + hp0) * vw0
                       + tanhf(acc[mi][ni][1] + hp1) * vw1;
            pr[mi][1] += tanhf(acc[mi][ni][2] + hp0) * vw0
                       + tanhf(acc[mi][ni][3] + hp1) * vw1;
        }
    }
#pragma unroll
    for (int mi = 0; mi < 4; ++mi)
#pragma unroll
        for (int h = 0; h < 2; ++h) {
            float p = pr[mi][h];
            p += __shfl_xor_sync(0xffffffffu, p, 1);
            p += __shfl_xor_sync(0xffffffffu, p, 2);
            if (tx == 0) red[wm * 64 + mi * 16 + h * 8 + ty][wn] = p;
        }
    __syncthreads();
    if (tid < 128)
        g_part[((size_t)(m0 + tid)) * 4 + nt] =
            red[tid][0] + red[tid][1] + red[tid][2] + red[tid][3];
}

// ---------------- masked softmax (sums 4 partials) --------------------------
__global__ void softmax_kernel(const int* __restrict__ mask, float* __restrict__ out) {
    int b = blockIdx.x;
    __shared__ float sh[Sdim];
    __shared__ float wr[8];
    int tid = threadIdx.x;

    float lmax = -1e30f;
    for (int s = tid; s < Sdim; s += 256) {
        float v;
        if (mask[b * Sdim + s] == 0) v = NEGV;
        else {
            float4 pp = ((const float4*)g_part)[b * Sdim + s];
            v = (pp.x + pp.y) + (pp.z + pp.w);
        }
        sh[s] = v;
        lmax = fmaxf(lmax, v);
    }
#pragma unroll
    for (int o = 16; o; o >>= 1) lmax = fmaxf(lmax, __shfl_xor_sync(~0u, lmax, o));
    if ((tid & 31) == 0) wr[tid >> 5] = lmax;
    __syncthreads();
    if (tid < 32) {
        float v = (tid < 8) ? wr[tid] : -1e30f;
#pragma unroll
        for (int o = 4; o; o >>= 1) v = fmaxf(v, __shfl_xor_sync(~0u, v, o));
        if (tid == 0) wr[0] = v;
    }
    __syncthreads();
    float gmax = wr[0];

    float lsum = 0.f;
    for (int s = tid; s < Sdim; s += 256) {
        float e = expf(sh[s] - gmax);
        sh[s] = e;
        lsum += e;
    }
    __syncthreads();
#pragma unroll
    for (int o = 16; o; o >>= 1) lsum += __shfl_xor_sync(~0u, lsum, o);
    if ((tid & 31) == 0) wr[tid >> 5] = lsum;
    __syncthreads();
    if (tid < 32) {
        float v = (tid < 8) ? wr[tid] : 0.f;
#pragma unroll
        for (int o = 4; o; o >>= 1) v += __shfl_xor_sync(~0u, v, o);
        if (tid == 0) wr[0] = v;
    }
    __syncthreads();
    float inv = 1.f / wr[0];
    float* w = out + Bdim * DEC;
    for (int s = tid; s < Sdim; s += 256) w[b * Sdim + s] = sh[s] * inv;
}

// ---------------- context (split-S, fp16 enc: half the traffic) -------------
__global__ void ctx_part_kernel(const float* __restrict__ w) {
    const __half2* encH2 = (const __half2*)g_encH4;
    int e2 = blockIdx.x * 256 + threadIdx.x;    // half2 index, 0..511
    int b = blockIdx.y, z = blockIdx.z;
    const __half2* ep = encH2 + ((size_t)b * Sdim + z * 256) * (ENC / 2) + e2;
    const float* wp = w + b * Sdim + z * 256;
    float ax = 0.f, ay = 0.f;
    for (int s = 0; s < 256; s += 8) {
#pragma unroll
        for (int u = 0; u < 8; ++u) {
            float2 v = __half22float2(ep[(size_t)(s + u) * (ENC / 2)]);
            float wv = wp[s + u];
            ax += wv * v.x;
            ay += wv * v.y;
        }
    }
    float2* dst = (float2*)g_ctx_part;
    dst[((size_t)(z * Bdim + b) << 9) + e2] = make_float2(ax, ay);
}
__global__ void ctx_reduce_kernel(float* __restrict__ out) {
    int id = blockIdx.x * 256 + threadIdx.x;
    float s = 0.f;
#pragma unroll
    for (int z = 0; z < 8; ++z) s += g_ctx_part[(z << 15) + id];
    out[id] = s;
}

// ---------------------------------------------------------------------------
extern "C" void kernel_launch(void* const* d_in, const int* in_sizes, int n_in,
                              void* d_out, int out_size) {
    const float* hidden = (const float*)d_in[0];
    const float* enc    = (const float*)d_in[1];
    const int*   mask   = (const int*)d_in[2];
    const float* attn_w = (const float*)d_in[3];
    const float* attn_b = (const float*)d_in[4];
    const float* v_w    = (const float*)d_in[5];
    float* out = (float*)d_out;   // [context(32x1024), weights(32x2048)]

    cudaFuncSetAttribute(energy_kernel,
                         cudaFuncAttributeMaxDynamicSharedMemorySize, DYN_SMEM);

    enc_to_half<<<4096, 256>>>(enc);
    we_to_half<<<128, 256>>>(attn_w);
    hproj_kernel<<<DEC, 256>>>(hidden, attn_w, attn_b);
    energy_kernel<<<dim3(4, 512), 256, DYN_SMEM>>>(v_w);
    softmax_kernel<<<Bdim, 256>>>(mask, out);
    ctx_part_kernel<<<dim3(2, Bdim, 8), 256>>>(out + Bdim * DEC);
    ctx_reduce_kernel<<<128, 256>>>(out);
}

// round 6
// speedup vs baseline: 6.7725x; 1.0577x over previous
#include <cuda_runtime.h>
#include <cuda_fp16.h>
#include <math.h>
#include <stdint.h>

#define Bdim 32
#define Sdim 2048
#define ENC  1024
#define DEC  1024
#define WTOT 2048
#define NEGV (-1e10f)

// ---------------- scratch ---------------------------------------------------
__device__ uint4 g_encH4[(size_t)Bdim * Sdim * ENC / 8]; // enc as fp16 [m][k]
__device__ uint4 g_weH4[DEC * ENC / 8];                  // w_e as fp16 [n][k]
__device__ float g_hpb[Bdim * DEC];                      // h_proj + bias
__device__ float g_part[(size_t)Bdim * Sdim * 8];        // per-(m, ntile) partials
__device__ float g_ctx_part[8 * Bdim * ENC];             // split-S ctx partials

// ---------------- helpers ----------------------------------------------------
__device__ __forceinline__ uint32_t smem_u32(const void* p) {
    uint32_t a;
    asm("{ .reg .u64 t; cvta.to.shared.u64 t, %1; cvt.u32.u64 %0, t; }"
        : "=r"(a) : "l"(p));
    return a;
}
__device__ __forceinline__ uint32_t h2pack(float x, float y) {
    __half2 h = __floats2half2_rn(x, y);
    return *(uint32_t*)&h;
}
__device__ __forceinline__ void mma_f16(float* d, uint32_t a0, uint32_t a1,
                                        uint32_t a2, uint32_t a3,
                                        uint32_t b0, uint32_t b1) {
    asm volatile(
        "mma.sync.aligned.m16n8k16.row.col.f32.f16.f16.f32 "
        "{%0,%1,%2,%3}, {%4,%5,%6,%7}, {%8,%9}, {%0,%1,%2,%3};"
        : "+f"(d[0]), "+f"(d[1]), "+f"(d[2]), "+f"(d[3])
        : "r"(a0), "r"(a1), "r"(a2), "r"(a3), "r"(b0), "r"(b1));
}
#define LDSM4(r0, r1, r2, r3, a) \
    asm volatile("ldmatrix.sync.aligned.m8n8.x4.shared.b16 {%0,%1,%2,%3}, [%4];" \
                 : "=r"(r0), "=r"(r1), "=r"(r2), "=r"(r3) : "r"(a))

// ---------------- fp32 -> fp16 conversions ----------------------------------
__global__ void enc_to_half(const float* __restrict__ enc) {
    size_t n8 = (size_t)Bdim * Sdim * ENC / 8;
    size_t stride = (size_t)gridDim.x * blockDim.x;
    for (size_t i = (size_t)blockIdx.x * blockDim.x + threadIdx.x; i < n8; i += stride) {
        float4 f0 = ((const float4*)enc)[2 * i];
        float4 f1 = ((const float4*)enc)[2 * i + 1];
        uint4 o;
        o.x = h2pack(f0.x, f0.y); o.y = h2pack(f0.z, f0.w);
        o.z = h2pack(f1.x, f1.y); o.w = h2pack(f1.z, f1.w);
        g_encH4[i] = o;
    }
}
__global__ void we_to_half(const float* __restrict__ attn_w) {
    int i = blockIdx.x * 256 + threadIdx.x;
    for (int j = i; j < DEC * ENC / 8; j += gridDim.x * 256) {
        int k = j >> 7, seg = j & 127;
        const float* src = attn_w + (size_t)k * WTOT + DEC + seg * 8;
        float4 f0 = ((const float4*)src)[0];
        float4 f1 = ((const float4*)src)[1];
        uint4 o;
        o.x = h2pack(f0.x, f0.y); o.y = h2pack(f0.z, f0.w);
        o.z = h2pack(f1.x, f1.y); o.w = h2pack(f1.z, f1.w);
        g_weH4[j] = o;
    }
}

// ---------------- h_proj + bias ---------------------------------------------
__global__ void hproj_kernel(const float* __restrict__ hidden,
                             const float* __restrict__ attn_w,
                             const float* __restrict__ attn_b) {
    int k = blockIdx.x;
    __shared__ float ws[DEC];
    for (int d = threadIdx.x; d < DEC; d += blockDim.x)
        ws[d] = attn_w[(size_t)k * WTOT + d];
    __syncthreads();
    int b = threadIdx.x >> 3, l = threadIdx.x & 7;
    const float* h = hidden + b * DEC;
    float p = 0.f;
#pragma unroll 8
    for (int d = l; d < DEC; d += 8) p += h[d] * ws[d];
    p += __shfl_down_sync(0xffffffffu, p, 4, 8);
    p += __shfl_down_sync(0xffffffffu, p, 2, 8);
    p += __shfl_down_sync(0xffffffffu, p, 1, 8);
    if (l == 0) g_hpb[b * DEC + k] = p + attn_b[k];
}

// ---------------- energy GEMM: fp16 mma.sync, 2 blocks/SM -------------------
// Block tile 128(M) x 128(N), warp tile 64x32 (8 warps, 2x4). K=1024 in 32
// chunks of 32 halves; 4-stage cp.async pipeline; 2 resident blocks per SM.
#define NCHUNK 32
#define A_STG_B 10240            // 128 rows * 80B
#define B_STG_B 10240            // 128 rows * 80B
#define STG_B   (A_STG_B + B_STG_B)
#define NSTAGE  4
#define DYN_SMEM (NSTAGE * STG_B)

__device__ __forceinline__ void issue_chunk(uint32_t sbase, int stage, int chunk,
                                            int m0, int n0, int tid) {
    uint32_t sb = sbase + stage * STG_B;
    int k0 = chunk * 32;
    const __half* encH = (const __half*)g_encH4;
    const __half* weH  = (const __half*)g_weH4;
#pragma unroll
    for (int t = 0; t < 4; ++t) {
        int u = t * 256 + tid;                  // 16B units: A 512, B 512
        const __half* g;
        uint32_t so;
        if (u < 512) {
            int r = u >> 2, seg = u & 3;
            so = (uint32_t)(r * 80 + seg * 16);
            g = encH + (size_t)(m0 + r) * ENC + k0 + seg * 8;
        } else {
            int v = u - 512;
            int r = v >> 2, seg = v & 3;
            so = (uint32_t)(A_STG_B + r * 80 + seg * 16);
            g = weH + (size_t)(n0 + r) * ENC + k0 + seg * 8;
        }
        asm volatile("cp.async.cg.shared.global [%0], [%1], 16;"
                     :: "r"(sb + so), "l"(g));
    }
    asm volatile("cp.async.commit_group;" ::: "memory");
}

struct Frag { uint32_t r[4]; };

__global__ void __launch_bounds__(256, 2) energy_kernel(const float* __restrict__ v_w) {
    extern __shared__ uint32_t sm[];
    __shared__ float red[128][4];
    uint32_t sbase = smem_u32(sm);

    int tid = threadIdx.x;
    int wid = tid >> 5, lane = tid & 31;
    int wm = wid >> 2, wn = wid & 3;            // 2x4 warp grid
    int ty = lane >> 2, tx = lane & 3;
    int nt = blockIdx.x, mt = blockIdx.y;
    int m0 = mt * 128, n0 = nt * 128;
    int bb = m0 >> 11;

    // ldmatrix per-lane base byte offsets (within a stage)
    int aRow = wm * 64 + (lane & 7) + (((lane >> 3) & 1) << 3);
    uint32_t aBase = (uint32_t)(aRow * 80 + ((lane >> 4) << 4));
    int bRow = wn * 32 + (lane & 7) + ((lane >> 4) << 3);
    uint32_t bBase = (uint32_t)(A_STG_B + bRow * 80 + (((lane >> 3) & 1) << 4));

    float acc[4][4][4];
#pragma unroll
    for (int mi = 0; mi < 4; ++mi)
#pragma unroll
        for (int ni = 0; ni < 4; ++ni)
#pragma unroll
            for (int c = 0; c < 4; ++c) acc[mi][ni][c] = 0.f;

    issue_chunk(sbase, 0, 0, m0, n0, tid);
    issue_chunk(sbase, 1, 1, m0, n0, tid);
    issue_chunk(sbase, 2, 2, m0, n0, tid);

    for (int i = 0; i < NCHUNK; ++i) {
        if (i < NCHUNK - 1) asm volatile("cp.async.wait_group 2;" ::: "memory");
        else                asm volatile("cp.async.wait_group 0;" ::: "memory");
        __syncthreads();
        if (i + 3 < NCHUNK)
            issue_chunk(sbase, (i + 3) & 3, i + 3, m0, n0, tid);

        uint32_t sb = sbase + (i & 3) * STG_B;
#pragma unroll
        for (int ks = 0; ks < 2; ++ks) {
            uint32_t koff = (uint32_t)(ks * 32);
            Frag bf[2];                          // p -> {2p.lo, 2p.hi, 2p+1.lo, 2p+1.hi}
            LDSM4(bf[0].r[0], bf[0].r[1], bf[0].r[2], bf[0].r[3],
                  sb + bBase + 0 * 1280 + koff);
            LDSM4(bf[1].r[0], bf[1].r[1], bf[1].r[2], bf[1].r[3],
                  sb + bBase + 1 * 1280 + koff);
            Frag af[2];
            LDSM4(af[0].r[0], af[0].r[1], af[0].r[2], af[0].r[3],
                  sb + aBase + 0 * 1280 + koff);
            LDSM4(af[1].r[0], af[1].r[1], af[1].r[2], af[1].r[3],
                  sb + aBase + 1 * 1280 + koff);
#pragma unroll
            for (int mi = 0; mi < 4; ++mi) {
                Frag a = af[mi & 1];
                if (mi + 2 < 4)
                    LDSM4(af[mi & 1].r[0], af[mi & 1].r[1],
                          af[mi & 1].r[2], af[mi & 1].r[3],
                          sb + aBase + (mi + 2) * 1280 + koff);
#pragma unroll
                for (int p = 0; p < 2; ++p) {
                    mma_f16(acc[mi][2 * p],     a.r[0], a.r[1], a.r[2], a.r[3],
                            bf[p].r[0], bf[p].r[1]);
                    mma_f16(acc[mi][2 * p + 1], a.r[0], a.r[1], a.r[2], a.r[3],
                            bf[p].r[2], bf[p].r[3]);
                }
            }
        }
    }

    // Epilogue: tanh + v_w partial reduction over this block's 128 cols.
    int colbase = n0 + wn * 32 + tx * 2;
    int hb = bb * DEC;
    float pr[4][2];
#pragma unroll
    for (int mi = 0; mi < 4; ++mi) { pr[mi][0] = 0.f; pr[mi][1] = 0.f; }
#pragma unroll
    for (int ni = 0; ni < 4; ++ni) {
        int c0 = colbase + ni * 8;
        float hp0 = g_hpb[hb + c0],  hp1 = g_hpb[hb + c0 + 1];
        float vw0 = v_w[c0],         vw1 = v_w[c0 + 1];
#pragma unroll
        for (int mi = 0; mi < 4; ++mi) {
            pr[mi][0] += tanhf(acc[mi][ni][0] + hp0) * vw0
                       + tanhf(acc[mi][ni][1] + hp1) * vw1;
            pr[mi][1] += tanhf(acc[mi][ni][2] + hp0) * vw0
                       + tanhf(acc[mi][ni][3] + hp1) * vw1;
        }
    }
#pragma unroll
    for (int mi = 0; mi < 4; ++mi)
#pragma unroll
        for (int h = 0; h < 2; ++h) {
            float p = pr[mi][h];
            p += __shfl_xor_sync(0xffffffffu, p, 1);
            p += __shfl_xor_sync(0xffffffffu, p, 2);
            if (tx == 0) red[wm * 64 + mi * 16 + h * 8 + ty][wn] = p;
        }
    __syncthreads();
    if (tid < 128)
        g_part[((size_t)(m0 + tid)) * 8 + nt] =
            red[tid][0] + red[tid][1] + red[tid][2] + red[tid][3];
}

// ---------------- masked softmax (sums 8 partials) --------------------------
__global__ void softmax_kernel(const int* __restrict__ mask, float* __restrict__ out) {
    int b = blockIdx.x;
    __shared__ float sh[Sdim];
    __shared__ float wr[8];
    int tid = threadIdx.x;

    float lmax = -1e30f;
    for (int s = tid; s < Sdim; s += 256) {
        float v;
        if (mask[b * Sdim + s] == 0) v = NEGV;
        else {
            const float4* pp = (const float4*)(g_part + ((size_t)(b * Sdim + s)) * 8);
            float4 p0 = pp[0], p1 = pp[1];
            v = ((p0.x + p0.y) + (p0.z + p0.w)) + ((p1.x + p1.y) + (p1.z + p1.w));
        }
        sh[s] = v;
        lmax = fmaxf(lmax, v);
    }
#pragma unroll
    for (int o = 16; o; o >>= 1) lmax = fmaxf(lmax, __shfl_xor_sync(~0u, lmax, o));
    if ((tid & 31) == 0) wr[tid >> 5] = lmax;
    __syncthreads();
    if (tid < 32) {
        float v = (tid < 8) ? wr[tid] : -1e30f;
#pragma unroll
        for (int o = 4; o; o >>= 1) v = fmaxf(v, __shfl_xor_sync(~0u, v, o));
        if (tid == 0) wr[0] = v;
    }
    __syncthreads();
    float gmax = wr[0];

    float lsum = 0.f;
    for (int s = tid; s < Sdim; s += 256) {
        float e = expf(sh[s] - gmax);
        sh[s] = e;
        lsum += e;
    }
    __syncthreads();
#pragma unroll
    for (int o = 16; o; o >>= 1) lsum += __shfl_xor_sync(~0u, lsum, o);
    if ((tid & 31) == 0) wr[tid >> 5] = lsum;
    __syncthreads();
    if (tid < 32) {
        float v = (tid < 8) ? wr[tid] : 0.f;
#pragma unroll
        for (int o = 4; o; o >>= 1) v += __shfl_xor_sync(~0u, v, o);
        if (tid == 0) wr[0] = v;
    }
    __syncthreads();
    float inv = 1.f / wr[0];
    float* w = out + Bdim * DEC;
    for (int s = tid; s < Sdim; s += 256) w[b * Sdim + s] = sh[s] * inv;
}

// ---------------- context (split-S, fp16 enc) -------------------------------
__global__ void ctx_part_kernel(const float* __restrict__ w) {
    const __half2* encH2 = (const __half2*)g_encH4;
    int e2 = blockIdx.x * 256 + threadIdx.x;    // half2 index, 0..511
    int b = blockIdx.y, z = blockIdx.z;
    const __half2* ep = encH2 + ((size_t)b * Sdim + z * 256) * (ENC / 2) + e2;
    const float* wp = w + b * Sdim + z * 256;
    float ax = 0.f, ay = 0.f;
    for (int s = 0; s < 256; s += 8) {
#pragma unroll
        for (int u = 0; u < 8; ++u) {
            float2 v = __half22float2(ep[(size_t)(s + u) * (ENC / 2)]);
            float wv = wp[s + u];
            ax += wv * v.x;
            ay += wv * v.y;
        }
    }
    float2* dst = (float2*)g_ctx_part;
    dst[((size_t)(z * Bdim + b) << 9) + e2] = make_float2(ax, ay);
}
__global__ void ctx_reduce_kernel(float* __restrict__ out) {
    int id = blockIdx.x * 256 + threadIdx.x;
    float s = 0.f;
#pragma unroll
    for (int z = 0; z < 8; ++z) s += g_ctx_part[(z << 15) + id];
    out[id] = s;
}

// ---------------------------------------------------------------------------
extern "C" void kernel_launch(void* const* d_in, const int* in_sizes, int n_in,
                              void* d_out, int out_size) {
    const float* hidden = (const float*)d_in[0];
    const float* enc    = (const float*)d_in[1];
    const int*   mask   = (const int*)d_in[2];
    const float* attn_w = (const float*)d_in[3];
    const float* attn_b = (const float*)d_in[4];
    const float* v_w    = (const float*)d_in[5];
    float* out = (float*)d_out;   // [context(32x1024), weights(32x2048)]

    cudaFuncSetAttribute(energy_kernel,
                         cudaFuncAttributeMaxDynamicSharedMemorySize, DYN_SMEM);

    enc_to_half<<<4096, 256>>>(enc);
    we_to_half<<<128, 256>>>(attn_w);
    hproj_kernel<<<DEC, 256>>>(hidden, attn_w, attn_b);
    energy_kernel<<<dim3(8, 512), 256, DYN_SMEM>>>(v_w);
    softmax_kernel<<<Bdim, 256>>>(mask, out);
    ctx_part_kernel<<<dim3(2, Bdim, 8), 256>>>(out + Bdim * DEC);
    ctx_reduce_kernel<<<128, 256>>>(out);
}